// round 3
// baseline (speedup 1.0000x reference)
#include <cuda_runtime.h>
#include <cuda_bf16.h>
#include <cstdint>

// Problem constants: I=16, O=8, J=4, B=16 -> n_in=1024, n_out=256, K=81.
// Each output element is hit by exactly 1-4 projectors:
//
// With qr = 32*i_r + 2*j_r, qc = 32*i_c + 2*j_c (float4/quad units), rb = 4*qr:
//   out[b, ij_r*4+ch, 4*gc .. +3] =
//       X4[rb+68+ch][qc+17]                       (center, always)
//     + (i_r==i_c)             * X4[rb+ 4+ch][qc+ 1]   (C group)
//     + (j_r==j_c)             * X4[rb+64+ch][qc+16]   (D group)
//     + (i_r==i_c && j_r==j_c) * X4[rb+   ch][qc+ 0]   (B group)
//
// Mapping: 1 thread = 1 output quad. Global id gid encodes
//   gid = ((b*64 + ij_r)*4 + ch_r)*64 + gc
// which is EXACTLY the linear output-quad index -> store address = gid.

#define QPB 262144   // quads per batch in X: 1024*256

__global__ __launch_bounds__(128, 16)
void pool2d_density_kernel(const float4* __restrict__ xq, float4* __restrict__ oq)
{
    const int gid  = blockIdx.x * 128 + threadIdx.x;   // 0..262143

    const int gc   = gid & 63;          // i_c*8 + j_c
    const int t    = gid >> 6;
    const int ch   = t & 3;             // ch_r
    const int ij_r = (t >> 2) & 63;
    const int b    = t >> 8;

    const int i_r = ij_r >> 3, j_r = ij_r & 7;
    const int i_c = gc   >> 3, j_c = gc   & 7;

    // all offsets fit comfortably in 32-bit
    const int base = (b << 18);                        // b * QPB
    const int rb   = (ij_r << 2) + (i_r << 5);         // 4*(32*i_r+2*j_r)... no:
    // 4*qr = 4*(32*i_r + 2*j_r) = 128*i_r + 8*j_r
    const int rb4  = (i_r << 7) + (j_r << 3);
    const int qc   = (i_c << 5) + (j_c << 1);

    // quad index = base + row*256 + col
    const int rowq = base + ((rb4 + ch) << 8);         // row rb4+ch, quad col 0

    // center (always)
    float4 acc = __ldg(&xq[rowq + (68 << 8) + qc + 17]);

    const bool im = (i_r == i_c);
    const bool jm = (j_r == j_c);

    if (im) {
        float4 v = __ldg(&xq[rowq + (4 << 8) + qc + 1]);
        acc.x += v.x; acc.y += v.y; acc.z += v.z; acc.w += v.w;
    }
    if (jm) {
        float4 v = __ldg(&xq[rowq + (64 << 8) + qc + 16]);
        acc.x += v.x; acc.y += v.y; acc.z += v.z; acc.w += v.w;
    }
    if (im && jm) {
        float4 v = __ldg(&xq[rowq + qc]);
        acc.x += v.x; acc.y += v.y; acc.z += v.z; acc.w += v.w;
    }

    // output quad linear index == gid (fully coalesced 128B stores per warp)
    oq[gid] = acc;
}

extern "C" void kernel_launch(void* const* d_in, const int* in_sizes, int n_in,
                              void* d_out, int out_size)
{
    const float4* x = (const float4*)d_in[0];   // (16, 1024, 1024) fp32 as quads
    float4* out = (float4*)d_out;               // (16, 256, 256) fp32 as quads

    // 262144 output quads, 1 per thread: 2048 blocks x 128 threads
    // (13.8 blocks/SM of 16 capacity -> high occupancy, fine-grain balance).
    pool2d_density_kernel<<<2048, 128>>>(x, out);
}

// round 4
// speedup vs baseline: 1.0433x; 1.0433x over previous
#include <cuda_runtime.h>
#include <cuda_bf16.h>
#include <cstdint>

// Problem constants: I=16, O=8, J=4, B=16 -> n_in=1024, n_out=256, K=81.
// Each output element is hit by exactly 1-4 projectors. With
//   rb4 = 128*i_r + 8*j_r (input row base), qc = 32*i_c + 2*j_c (quad col):
//   out[b, ij_r*4+ch, 4*gc..+3] =
//       X4[rb4+68+ch][qc+17]                       (center, always)
//     + [i_r==i_c]             X4[rb4+ 4+ch][qc+ 1]   (C)
//     + [j_r==j_c]             X4[rb4+64+ch][qc+16]   (D)
//     + [i_r==i_c && j_r==j_c] X4[rb4+   ch][qc+ 0]   (B)
//
// Branch-free: disabled terms load the CENTER address again (L1 pending-hit,
// no extra DRAM sectors) and are zeroed via FMA with a 0/1 mask. Every thread
// issues exactly 4 independent LDG.128s up front (MLP=4, no BSSY/BSYNC).

__global__ __launch_bounds__(256, 8)
void pool2d_density_kernel(const float4* __restrict__ xq, float4* __restrict__ oq)
{
    const int gid  = blockIdx.x * 256 + threadIdx.x;   // 0..262143 = output quad

    const int gc   = gid & 63;          // i_c*8 + j_c
    const int t    = gid >> 6;
    const int ch   = t & 3;             // ch_r
    const int ij_r = (t >> 2) & 63;     // i_r*8 + j_r
    const int b    = t >> 8;

    const int i_r = ij_r >> 3, j_r = ij_r & 7;
    const int i_c = gc   >> 3, j_c = gc   & 7;

    const int rb4  = (i_r << 7) + (j_r << 3);          // 128*i_r + 8*j_r
    const int qc   = (i_c << 5) + (j_c << 1);          // 32*i_c + 2*j_c
    // quad index of (row rb4+ch, col 0) within full tensor
    const int rowq = (b << 18) + ((rb4 + ch) << 8);

    const bool im = (i_r == i_c);
    const bool jm = (j_r == j_c);

    const int a0 = rowq + (68 << 8) + qc + 17;                 // center
    const int aC = im         ? rowq + (4  << 8) + qc + 1  : a0;
    const int aD = jm         ? rowq + (64 << 8) + qc + 16 : a0;
    const int aB = (im && jm) ? rowq + qc                  : a0;

    // four independent 16B loads, issued back-to-back
    float4 v0 = __ldg(&xq[a0]);
    float4 vC = __ldg(&xq[aC]);
    float4 vD = __ldg(&xq[aD]);
    float4 vB = __ldg(&xq[aB]);

    const float mi = im         ? 1.0f : 0.0f;
    const float mj = jm         ? 1.0f : 0.0f;
    const float mb = (im && jm) ? 1.0f : 0.0f;

    float4 acc;
    acc.x = fmaf(mi, vC.x, v0.x);
    acc.y = fmaf(mi, vC.y, v0.y);
    acc.z = fmaf(mi, vC.z, v0.z);
    acc.w = fmaf(mi, vC.w, v0.w);
    acc.x = fmaf(mj, vD.x, acc.x);
    acc.y = fmaf(mj, vD.y, acc.y);
    acc.z = fmaf(mj, vD.z, acc.z);
    acc.w = fmaf(mj, vD.w, acc.w);
    acc.x = fmaf(mb, vB.x, acc.x);
    acc.y = fmaf(mb, vB.y, acc.y);
    acc.z = fmaf(mb, vB.z, acc.z);
    acc.w = fmaf(mb, vB.w, acc.w);

    // output quad linear index == gid (fully coalesced 128B stores per warp)
    oq[gid] = acc;
}

extern "C" void kernel_launch(void* const* d_in, const int* in_sizes, int n_in,
                              void* d_out, int out_size)
{
    const float4* x = (const float4*)d_in[0];   // (16, 1024, 1024) fp32 as quads
    float4* out = (float4*)d_out;               // (16, 256, 256) fp32 as quads

    // 262144 output quads, 1 per thread: 1024 blocks x 256 threads
    pool2d_density_kernel<<<1024, 256>>>(x, out);
}